// round 14
// baseline (speedup 1.0000x reference)
#include <cuda_runtime.h>
#include <cuda_bf16.h>
#include <cstdint>

#define TT    2048
#define HIDD  3584
#define NHQ   28
#define NKVH  4
#define HDIM  128
#define GQA   7
#define NQKV  4608
#define ASCALE 0.08838834764831845f
#define SCALE_L2E 0.12751743f          // ASCALE * log2(e)
#define LOG2_THETA 19.931568569324174f

// ------------------------- static device scratch ----------------------------
__device__ __nv_bfloat16 g_hsex  [(size_t)TT * 2 * HIDD];
__device__ __nv_bfloat16 g_wqkvex[(size_t)NQKV * 2 * HIDD];
__device__ float         g_bqkv  [NQKV];
__device__ __nv_bfloat16 g_woex  [(size_t)HIDD * 2 * HIDD];
__device__ __nv_bfloat16 g_qex   [(size_t)NHQ * TT * 2 * HDIM];   // pre-scaled by SCALE_L2E
__device__ __nv_bfloat16 g_kex   [(size_t)NKVH * TT * 2 * HDIM];
__device__ __nv_bfloat16 g_vex   [(size_t)NKVH * HDIM * 2 * TT];  // V^T [4][128][hi|lo]
__device__ __nv_bfloat16 g_attnex[(size_t)TT * 2 * HIDD];
__device__ float         g_rtab  [(size_t)TT * 128];              // [t][cos(64)|sin(64)]

// ------------------------- helpers ------------------------------------------
__device__ __forceinline__ void split2(float x, __nv_bfloat16& h, __nv_bfloat16& l) {
    h = __float2bfloat16(x);
    l = __float2bfloat16(x - __bfloat162float(h));
}

__device__ __forceinline__ uint32_t smem_u32(const void* p) {
    uint32_t a;
    asm("{ .reg .u64 t; cvta.to.shared.u64 t, %1; cvt.u32.u64 %0, t; }" : "=r"(a) : "l"(p));
    return a;
}

__device__ __forceinline__ void cp16(uint32_t dst, const void* src) {
    asm volatile("cp.async.cg.shared.global [%0], [%1], 16;" :: "r"(dst), "l"(src));
}

__device__ __forceinline__ float ex2(float x) {
    float y;
    asm("ex2.approx.ftz.f32 %0, %1;" : "=f"(y) : "f"(x));
    return y;
}

__device__ __forceinline__ void hmma(float* c, const uint32_t* a, const uint32_t* b) {
    asm volatile(
        "mma.sync.aligned.m16n8k16.row.col.f32.bf16.bf16.f32 "
        "{%0,%1,%2,%3}, {%4,%5,%6,%7}, {%8,%9}, {%0,%1,%2,%3};"
        : "+f"(c[0]), "+f"(c[1]), "+f"(c[2]), "+f"(c[3])
        : "r"(a[0]), "r"(a[1]), "r"(a[2]), "r"(a[3]), "r"(b[0]), "r"(b[1]));
}

__device__ __forceinline__ void ldx4(uint32_t* r, uint32_t addr) {
    asm volatile("ldmatrix.sync.aligned.m8n8.x4.shared.b16 {%0,%1,%2,%3}, [%4];"
                 : "=r"(r[0]), "=r"(r[1]), "=r"(r[2]), "=r"(r[3]) : "r"(addr));
}

__device__ __forceinline__ uint32_t packbf(float a, float b) {
    __nv_bfloat162 v = __floats2bfloat162_rn(a, b);
    return *reinterpret_cast<uint32_t*>(&v);
}

__device__ __forceinline__ void packsplit(float a, float b, uint32_t& hi, uint32_t& lo) {
    __nv_bfloat16 ha = __float2bfloat16(a), hb = __float2bfloat16(b);
    float la = a - __bfloat162float(ha);
    float lb = b - __bfloat162float(hb);
    __nv_bfloat162 hv; hv.x = ha; hv.y = hb;
    hi = *reinterpret_cast<uint32_t*>(&hv);
    lo = packbf(la, lb);
}

// ------------------------- HMMA split-bf16 GEMM ------------------------------
// QKV=false: standard fp32 epilogue (C,ldc,alpha used).
// QKV=true : fused epilogue -> rope/split to qex/kex, transpose/split to vex.
#define APAD   40
#define STAGES 4

template <bool QKV>
__global__ __launch_bounds__(256, 2) void mma_gemm(
    const __nv_bfloat16* __restrict__ A,
    const __nv_bfloat16* __restrict__ B,
    const float* __restrict__ bias,
    float* __restrict__ C, int ldc,
    int Khalf, float alpha,
    const float* __restrict__ rtab,
    __nv_bfloat16* __restrict__ qex,
    __nv_bfloat16* __restrict__ kex,
    __nv_bfloat16* __restrict__ vex)
{
    constexpr int MI     = 4;
    constexpr int ACP    = 2;
    constexpr int ABYTES = 128 * APAD * 2;
    constexpr int BBYTES = 128 * APAD * 2;

    extern __shared__ char sm[];
    const uint32_t sA = smem_u32(sm);
    const uint32_t sB = sA + STAGES * ABYTES;

    const int t   = threadIdx.x;
    const int wid = t >> 5, lid = t & 31;
    const int wm  = wid >> 2;
    const int wn  = wid & 3;
    const long lda = 2L * Khalf;
    const int m0 = blockIdx.y * 128, n0 = blockIdx.x * 128;

    A += (long)m0 * lda;
    B += (long)n0 * lda;

    const int a_row = (lid & 7) + ((lid >> 3) & 1) * 8;
    const int a_c8  = (lid >> 4) * 8;
    const int b4r = (lid & 7) + ((lid >> 4) & 1) * 8;
    const int b4c = ((lid >> 3) & 1) * 8;
    const uint32_t aBase  = sA + ((wm * 64 + a_row) * APAD + a_c8) * 2;
    const uint32_t bBase4 = sB + ((wn * 32 + b4r) * APAD + b4c) * 2;

    const int nk  = Khalf >> 5;
    const int nk3 = 3 * nk;

    float acc[MI][4][4];
#pragma unroll
    for (int i = 0; i < MI; i++)
#pragma unroll
        for (int j = 0; j < 4; j++)
#pragma unroll
            for (int r = 0; r < 4; r++) acc[i][j][r] = 0.0f;

    auto issue = [&](int c) {
        int r  = c / nk;
        int kk = c - r * nk;
        long ao = (long)((r == 1) ? Khalf : 0) + (long)kk * 32;
        long bo = (long)((r == 2) ? Khalf : 0) + (long)kk * 32;
        uint32_t stA = (uint32_t)(c & (STAGES - 1)) * ABYTES;
        uint32_t stB = (uint32_t)(c & (STAGES - 1)) * BBYTES;
#pragma unroll
        for (int i = 0; i < ACP; i++) {
            int idx = t + i * 256, row = idx >> 2, q = (idx & 3) * 8;
            cp16(sA + stA + (row * APAD + q) * 2, A + (long)row * lda + ao + q);
        }
#pragma unroll
        for (int i = 0; i < 2; i++) {
            int idx = t + i * 256, row = idx >> 2, q = (idx & 3) * 8;
            cp16(sB + stB + (row * APAD + q) * 2, B + (long)row * lda + bo + q);
        }
    };

#pragma unroll
    for (int s = 0; s < STAGES - 1; s++) {
        issue(s);
        asm volatile("cp.async.commit_group;" ::: "memory");
    }

    for (int c = 0; c < nk3; c++) {
        asm volatile("cp.async.wait_group %0;" :: "n"(STAGES - 2) : "memory");
        __syncthreads();

        const uint32_t stA = (uint32_t)(c & (STAGES - 1)) * ABYTES;
        const uint32_t stB = (uint32_t)(c & (STAGES - 1)) * BBYTES;
#pragma unroll
        for (int ks = 0; ks < 2; ks++) {
            uint32_t af[MI][4], bf[2][4];
#pragma unroll
            for (int mi = 0; mi < MI; mi++)
                ldx4(af[mi], aBase + stA + (mi * 16 * APAD + ks * 16) * 2);
#pragma unroll
            for (int njp = 0; njp < 2; njp++)
                ldx4(bf[njp], bBase4 + stB + (njp * 16 * APAD + ks * 16) * 2);
#pragma unroll
            for (int mi = 0; mi < MI; mi++)
#pragma unroll
                for (int njp = 0; njp < 2; njp++) {
                    hmma(acc[mi][2 * njp],     af[mi], bf[njp]);
                    hmma(acc[mi][2 * njp + 1], af[mi], bf[njp] + 2);
                }
        }
        if (c + STAGES - 1 < nk3) issue(c + STAGES - 1);
        asm volatile("cp.async.commit_group;" ::: "memory");
    }

    const int er = lid >> 2;
    const int ec = (lid & 3) * 2;

    if (!QKV) {
        // standard fp32 epilogue
#pragma unroll
        for (int nj = 0; nj < 4; nj++) {
            int col = n0 + wn * 32 + nj * 8 + ec;
            float b0 = 0.f, b1 = 0.f;
            if (bias) { b0 = __ldg(bias + col); b1 = __ldg(bias + col + 1); }
#pragma unroll
            for (int mi = 0; mi < MI; mi++) {
                int row0 = m0 + wm * 64 + mi * 16 + er;
                float2 v0 = { alpha * acc[mi][nj][0] + b0, alpha * acc[mi][nj][1] + b1 };
                float2 v1 = { alpha * acc[mi][nj][2] + b0, alpha * acc[mi][nj][3] + b1 };
                *(float2*)(C + (long)row0 * ldc + col)       = v0;
                *(float2*)(C + (long)(row0 + 8) * ldc + col) = v1;
            }
        }
        return;
    }

    // ---- fused QKV epilogue: stage tile (+bias) in smem, then rope/split ----
    __syncthreads();                     // mainloop smem reads done
    float* smt = (float*)sm;             // [128][129]
#pragma unroll
    for (int nj = 0; nj < 4; nj++) {
        int col = wn * 32 + nj * 8 + ec;
        float b0 = __ldg(bias + n0 + col);
        float b1 = __ldg(bias + n0 + col + 1);
#pragma unroll
        for (int mi = 0; mi < MI; mi++) {
            int row0 = wm * 64 + mi * 16 + er;
            smt[row0 * 129 + col]           = acc[mi][nj][0] + b0;
            smt[row0 * 129 + col + 1]       = acc[mi][nj][1] + b1;
            smt[(row0 + 8) * 129 + col]     = acc[mi][nj][2] + b0;
            smt[(row0 + 8) * 129 + col + 1] = acc[mi][nj][3] + b1;
        }
    }
    __syncthreads();

    const int hsel = blockIdx.x;         // 0..35: Q(0-27), K(28-31), V(32-35)
    if (hsel < NHQ + NKVH) {
        const float scale = (hsel < NHQ) ? SCALE_L2E : 1.0f;
        __nv_bfloat16* ob = (hsel < NHQ)
            ? qex + (long)hsel * TT * (2 * HDIM)
            : kex + (long)(hsel - NHQ) * TT * (2 * HDIM);
#pragma unroll
        for (int i = 0; i < 32; i++) {
            int idx = t + i * 256, row = idx >> 6, d = idx & 63;
            int tt = m0 + row;
            float c = rtab[tt * 128 + d];
            float s = rtab[tt * 128 + 64 + d];
            float x1 = smt[row * 129 + d];
            float x2 = smt[row * 129 + d + 64];
            float y1 = (x1 * c - x2 * s) * scale;
            float y2 = (x2 * c + x1 * s) * scale;
            __nv_bfloat16 h1, l1, h2, l2;
            split2(y1, h1, l1); split2(y2, h2, l2);
            __nv_bfloat16* o = ob + (long)tt * (2 * HDIM);
            o[d] = h1; o[d + 64] = h2;
            o[128 + d] = l1; o[192 + d] = l2;
        }
    } else {
        __nv_bfloat16* vb = vex + (long)(hsel - NHQ - NKVH) * HDIM * (2 * TT);
#pragma unroll
        for (int i = 0; i < 32; i++) {
            int idx = t + i * 256, d = idx >> 6, tp = idx & 63;
            float x0 = smt[(2 * tp) * 129 + d];
            float x1 = smt[(2 * tp + 1) * 129 + d];
            uint32_t hi, lo;
            packsplit(x0, x1, hi, lo);
            long base = (long)d * (2 * TT) + m0 + 2 * tp;
            *(uint32_t*)(vb + base)      = hi;
            *(uint32_t*)(vb + base + TT) = lo;
        }
    }
}

// ------------------------- fused flash attention -----------------------------
#define KPAD 264
#define VPAD 136
#define FSM_BYTES ((128 * KPAD * 2 + 128 * VPAD * 2) * 2)   // 204800
#define NCHUNK (TT / 128)

__global__ __launch_bounds__(256, 1) void flash_attn(
    const __nv_bfloat16* __restrict__ Qe,
    const __nv_bfloat16* __restrict__ Ke,
    const __nv_bfloat16* __restrict__ Ve,
    __nv_bfloat16* __restrict__ Oex)
{
    extern __shared__ char fsm[];
    const uint32_t uQ  = smem_u32(fsm);
    const uint32_t uK  = uQ + 128 * KPAD * 2;
    const uint32_t uVh = uK + 128 * KPAD * 2;
    const uint32_t uVl = uVh + 128 * VPAD * 2;

    const int t = threadIdx.x, wid = t >> 5, lid = t & 31;
    const int h = blockIdx.y, hk = h / GQA;
    const int q0 = blockIdx.x * 128;

    const __nv_bfloat16* Qg = Qe + ((long)h * TT + q0) * 256;
    const __nv_bfloat16* Kg = Ke + (long)hk * TT * 256;
    const __nv_bfloat16* Vg = Ve + (long)hk * HDIM * (2 * TT);

    auto loadK = [&](int kc) {
        const __nv_bfloat16* src = Kg + (long)kc * 128 * 256;
#pragma unroll
        for (int i = 0; i < 16; i++) {
            int idx = t + i * 256, row = idx >> 5, ce = (idx & 31) * 8;
            cp16(uK + (row * KPAD + ce) * 2, src + (long)row * 256 + ce);
        }
    };
    auto loadV = [&](int kc) {
#pragma unroll
        for (int i = 0; i < 8; i++) {
            int idx = t + i * 256, row = idx >> 4, ce = (idx & 15) * 8;
            const __nv_bfloat16* s = Vg + (long)row * (2 * TT) + kc * 128 + ce;
            cp16(uVh + (row * VPAD + ce) * 2, s);
            cp16(uVl + (row * VPAD + ce) * 2, s + TT);
        }
    };

#pragma unroll
    for (int i = 0; i < 16; i++) {
        int idx = t + i * 256, row = idx >> 5, ce = (idx & 31) * 8;
        cp16(uQ + (row * KPAD + ce) * 2, Qg + (long)row * 256 + ce);
    }
    loadK(0);
    loadV(0);
    asm volatile("cp.async.commit_group;" ::: "memory");
    asm volatile("cp.async.wait_group 0;" ::: "memory");
    __syncthreads();

    const int a_row = (lid & 7) + ((lid >> 3) & 1) * 8;
    const int a_c8  = (lid >> 4) * 8;
    const int b4r   = (lid & 7) + ((lid >> 4) & 1) * 8;
    const int b4c   = ((lid >> 3) & 1) * 8;
    const uint32_t aQbase = uQ + ((wid * 16 + a_row) * KPAD + a_c8) * 2;

    float oacc[16][4];
#pragma unroll
    for (int nj = 0; nj < 16; nj++)
#pragma unroll
        for (int r = 0; r < 4; r++) oacc[nj][r] = 0.0f;
    float m0 = -1e30f, m1 = -1e30f, l0 = 0.0f, l1 = 0.0f;

    for (int kc = 0; kc < NCHUNK; kc++) {
        if (kc > 0) {
            asm volatile("cp.async.wait_group 1;" ::: "memory");
            __syncthreads();
        }

        float sacc[16][4];
#pragma unroll
        for (int nj = 0; nj < 16; nj++)
#pragma unroll
            for (int r = 0; r < 4; r++) sacc[nj][r] = 0.0f;

#pragma unroll
        for (int ks = 0; ks < 8; ks++) {
            uint32_t aqh[4], aql[4];
            ldx4(aqh, aQbase + (ks * 16) * 2);
            ldx4(aql, aQbase + (128 + ks * 16) * 2);
#pragma unroll
            for (int njp = 0; njp < 8; njp++) {
                uint32_t bh[4], bl[4];
                ldx4(bh, uK + ((njp * 16 + b4r) * KPAD + ks * 16 + b4c) * 2);
                ldx4(bl, uK + ((njp * 16 + b4r) * KPAD + 128 + ks * 16 + b4c) * 2);
                hmma(sacc[2 * njp],     aqh, bh);
                hmma(sacc[2 * njp],     aql, bh);
                hmma(sacc[2 * njp],     aqh, bl);
                hmma(sacc[2 * njp + 1], aqh, bh + 2);
                hmma(sacc[2 * njp + 1], aql, bh + 2);
                hmma(sacc[2 * njp + 1], aqh, bl + 2);
            }
        }
        __syncthreads();
        if (kc + 1 < NCHUNK) {
            loadK(kc + 1);
            asm volatile("cp.async.commit_group;" ::: "memory");
        }

        float mx0 = -1e30f, mx1 = -1e30f;
#pragma unroll
        for (int nj = 0; nj < 16; nj++) {
            mx0 = fmaxf(mx0, fmaxf(sacc[nj][0], sacc[nj][1]));
            mx1 = fmaxf(mx1, fmaxf(sacc[nj][2], sacc[nj][3]));
        }
        mx0 = fmaxf(mx0, __shfl_xor_sync(0xffffffffu, mx0, 1));
        mx0 = fmaxf(mx0, __shfl_xor_sync(0xffffffffu, mx0, 2));
        mx1 = fmaxf(mx1, __shfl_xor_sync(0xffffffffu, mx1, 1));
        mx1 = fmaxf(mx1, __shfl_xor_sync(0xffffffffu, mx1, 2));
        float nm0 = fmaxf(m0, mx0), nm1 = fmaxf(m1, mx1);
        float sc0 = ex2(m0 - nm0), sc1 = ex2(m1 - nm1);
        m0 = nm0; m1 = nm1;
        l0 *= sc0; l1 *= sc1;
#pragma unroll
        for (int nj = 0; nj < 16; nj++) {
            oacc[nj][0] *= sc0; oacc[nj][1] *= sc0;
            oacc[nj][2] *= sc1; oacc[nj][3] *= sc1;
        }

        if (kc + 1 < NCHUNK) {
            asm volatile("cp.async.wait_group 1;" ::: "memory");
        } else {
            asm volatile("cp.async.wait_group 0;" ::: "memory");
        }
        __syncthreads();

#pragma unroll
        for (int ks = 0; ks < 8; ks++) {
            float e00 = ex2(sacc[2 * ks][0]     - m0);
            float e01 = ex2(sacc[2 * ks][1]     - m0);
            float e02 = ex2(sacc[2 * ks][2]     - m1);
            float e03 = ex2(sacc[2 * ks][3]     - m1);
            float e10 = ex2(sacc[2 * ks + 1][0] - m0);
            float e11 = ex2(sacc[2 * ks + 1][1] - m0);
            float e12 = ex2(sacc[2 * ks + 1][2] - m1);
            float e13 = ex2(sacc[2 * ks + 1][3] - m1);
            l0 += e00 + e01 + e10 + e11;
            l1 += e02 + e03 + e12 + e13;
            uint32_t ph[4], pl[4];
            packsplit(e00, e01, ph[0], pl[0]);
            packsplit(e02, e03, ph[1], pl[1]);
            packsplit(e10, e11, ph[2], pl[2]);
            packsplit(e12, e13, ph[3], pl[3]);
#pragma unroll
            for (int njp = 0; njp < 8; njp++) {
                uint32_t bvh[4], bvl[4];
                ldx4(bvh, uVh + ((njp * 16 + b4r) * VPAD + ks * 16 + b4c) * 2);
                ldx4(bvl, uVl + ((njp * 16 + b4r) * VPAD + ks * 16 + b4c) * 2);
                hmma(oacc[2 * njp],     ph, bvh);
                hmma(oacc[2 * njp],     pl, bvh);
                hmma(oacc[2 * njp],     ph, bvl);
                hmma(oacc[2 * njp + 1], ph, bvh + 2);
                hmma(oacc[2 * njp + 1], pl, bvh + 2);
                hmma(oacc[2 * njp + 1], ph, bvl + 2);
            }
        }
        __syncthreads();
        if (kc + 1 < NCHUNK) {
            loadV(kc + 1);
            asm volatile("cp.async.commit_group;" ::: "memory");
        }
    }

    l0 += __shfl_xor_sync(0xffffffffu, l0, 1);
    l0 += __shfl_xor_sync(0xffffffffu, l0, 2);
    l1 += __shfl_xor_sync(0xffffffffu, l1, 1);
    l1 += __shfl_xor_sync(0xffffffffu, l1, 2);
    const float inv0 = 1.0f / l0, inv1 = 1.0f / l1;

    const int gr = lid >> 2;
    const int ec = (lid & 3) * 2;
    const long r0 = q0 + wid * 16 + gr;
    const long r1 = r0 + 8;
#pragma unroll
    for (int nj = 0; nj < 16; nj++) {
        int col = h * HDIM + nj * 8 + ec;
        uint32_t hi, lo;
        packsplit(oacc[nj][0] * inv0, oacc[nj][1] * inv0, hi, lo);
        *(uint32_t*)(Oex + r0 * (2 * HIDD) + col)        = hi;
        *(uint32_t*)(Oex + r0 * (2 * HIDD) + HIDD + col) = lo;
        packsplit(oacc[nj][2] * inv1, oacc[nj][3] * inv1, hi, lo);
        *(uint32_t*)(Oex + r1 * (2 * HIDD) + col)        = hi;
        *(uint32_t*)(Oex + r1 * (2 * HIDD) + HIDD + col) = lo;
    }
}

// ------------------------- conversion kernels -------------------------------
__global__ void split_rows(const float* __restrict__ in, __nv_bfloat16* __restrict__ out,
                           int K)
{
    const int r = blockIdx.y;
    const int k = (blockIdx.x * 256 + threadIdx.x) * 4;
    if (k >= K) return;
    float4 x = *(const float4*)(in + (long)r * K + k);
    __nv_bfloat16 h0,l0,h1,l1,h2,l2,h3,l3;
    split2(x.x,h0,l0); split2(x.y,h1,l1); split2(x.z,h2,l2); split2(x.w,h3,l3);
    __nv_bfloat16* oh = out + (long)r * 2 * K + k;
    oh[0]=h0; oh[1]=h1; oh[2]=h2; oh[3]=h3;
    __nv_bfloat16* ol = oh + K;
    ol[0]=l0; ol[1]=l1; ol[2]=l2; ol[3]=l3;
}

// merged weight transpose-split: one launch for wq|wk|wv|wo.
__global__ void split_transpose_w(const float* __restrict__ wq, const float* __restrict__ wk,
                                  const float* __restrict__ wv, const float* __restrict__ wo,
                                  __nv_bfloat16* __restrict__ wqkvex,
                                  __nv_bfloat16* __restrict__ woex)
{
    __shared__ float smt[64][65];
    int yb = blockIdx.y;
    const float* src; int ldin; __nv_bfloat16* dst;
    if (yb < 56)       { src = wq; ldin = HIDD; dst = wqkvex; }
    else if (yb < 64)  { src = wk; ldin = 512;  dst = wqkvex + (size_t)HIDD * 2 * HIDD;        yb -= 56; }
    else if (yb < 72)  { src = wv; ldin = 512;  dst = wqkvex + (size_t)(HIDD + 512) * 2 * HIDD; yb -= 64; }
    else               { src = wo; ldin = HIDD; dst = woex;                                     yb -= 72; }

    const int k0 = blockIdx.x * 64, n0 = yb * 64;
    const int tx = threadIdx.x, ty = threadIdx.y;

#pragma unroll
    for (int rr = 0; rr < 8; rr++) {
        int i = ty + rr * 8;
        float2 v = *(const float2*)(src + (long)(k0 + i) * ldin + n0 + tx * 2);
        smt[i][tx * 2]     = v.x;
        smt[i][tx * 2 + 1] = v.y;
    }
    __syncthreads();

#pragma unroll
    for (int rr = 0; rr < 8; rr++) {
        int j = ty + rr * 8;
        float x0 = smt[tx * 2][j];
        float x1 = smt[tx * 2 + 1][j];
        uint32_t hi, lo;
        packsplit(x0, x1, hi, lo);
        long base = (long)(n0 + j) * (2L * HIDD) + k0 + tx * 2;
        *(uint32_t*)(dst + base)        = hi;
        *(uint32_t*)(dst + base + HIDD) = lo;
    }
}

__global__ void rope_tab(const int* __restrict__ pos, float* __restrict__ tab)
{
    int t = blockIdx.x, d = threadIdx.x;
    float p = (float)pos[t];
    float ang = p * exp2f(-(float)d * (LOG2_THETA / 64.0f));
    float s, c;
    sincosf(ang, &s, &c);
    tab[t * 128 + d]      = c;
    tab[t * 128 + 64 + d] = s;
}

__global__ void concat_bias(const float* __restrict__ bq, const float* __restrict__ bk,
                            const float* __restrict__ bv, float* __restrict__ o)
{
    int i = blockIdx.x * 256 + threadIdx.x;
    if (i >= NQKV) return;
    if (i < HIDD)            o[i] = bq[i];
    else if (i < HIDD + 512) o[i] = bk[i - HIDD];
    else                     o[i] = bv[i - HIDD - 512];
}

// ------------------------- launch -------------------------------------------
extern "C" void kernel_launch(void* const* d_in, const int* in_sizes, int n_in,
                              void* d_out, int out_size)
{
    const int*   pos = (const int*)d_in[0];
    const float* hs  = (const float*)d_in[1];
    const float* wq  = (const float*)d_in[2];
    const float* bq  = (const float*)d_in[3];
    const float* wk  = (const float*)d_in[4];
    const float* bk  = (const float*)d_in[5];
    const float* wv  = (const float*)d_in[6];
    const float* bv  = (const float*)d_in[7];
    const float* wo  = (const float*)d_in[8];
    float* out = (float*)d_out;

    __nv_bfloat16 *hsex, *wqkvex, *woex, *qex, *kex, *vex, *attnex;
    float *bqkv, *rtab;
    cudaGetSymbolAddress((void**)&hsex,   g_hsex);
    cudaGetSymbolAddress((void**)&wqkvex, g_wqkvex);
    cudaGetSymbolAddress((void**)&bqkv,   g_bqkv);
    cudaGetSymbolAddress((void**)&woex,   g_woex);
    cudaGetSymbolAddress((void**)&qex,    g_qex);
    cudaGetSymbolAddress((void**)&kex,    g_kex);
    cudaGetSymbolAddress((void**)&vex,    g_vex);
    cudaGetSymbolAddress((void**)&attnex, g_attnex);
    cudaGetSymbolAddress((void**)&rtab,   g_rtab);

    const int smem128 = STAGES * (128 + 128) * APAD * 2;   // 81920 >= 128*129*4
    cudaFuncSetAttribute(mma_gemm<false>, cudaFuncAttributeMaxDynamicSharedMemorySize, smem128);
    cudaFuncSetAttribute(mma_gemm<true>,  cudaFuncAttributeMaxDynamicSharedMemorySize, smem128);
    cudaFuncSetAttribute(flash_attn,      cudaFuncAttributeMaxDynamicSharedMemorySize, FSM_BYTES);

    // ---- operand conversions ----
    split_rows<<<dim3((HIDD/4 + 255) / 256, TT), 256>>>(hs, hsex, HIDD);
    split_transpose_w<<<dim3(HIDD/64, 128), dim3(32,8)>>>(wq, wk, wv, wo, wqkvex, woex);
    concat_bias<<<(NQKV + 255) / 256, 256>>>(bq, bk, bv, bqkv);
    rope_tab<<<TT, 64>>>(pos, rtab);

    // ---- fused QKV projection + rope/split/transpose epilogue ----
    mma_gemm<true><<<dim3(NQKV/128, TT/128, 1), 256, smem128>>>(
        hsex, wqkvex, bqkv, nullptr, 0, HIDD, 1.0f, rtab, qex, kex, vex);

    // ---- fused attention ----
    flash_attn<<<dim3(TT/128, NHQ), 256, FSM_BYTES>>>(qex, kex, vex, attnex);

    // ---- out = attn @ wo ----
    mma_gemm<false><<<dim3(HIDD/128, TT/128, 1), 256, smem128>>>(
        attnex, woex, nullptr, out, HIDD, HIDD, 1.0f, nullptr, nullptr, nullptr, nullptr);
}

// round 15
// speedup vs baseline: 1.0177x; 1.0177x over previous
#include <cuda_runtime.h>
#include <cuda_bf16.h>
#include <cstdint>

#define TT    2048
#define HIDD  3584
#define NHQ   28
#define NKVH  4
#define HDIM  128
#define GQA   7
#define NQKV  4608
#define ASCALE 0.08838834764831845f
#define SCALE_L2E 0.12751743f          // ASCALE * log2(e)
#define LOG2_THETA 19.931568569324174f

// ------------------------- static device scratch ----------------------------
__device__ __nv_bfloat16 g_hsex  [(size_t)TT * 2 * HIDD];
__device__ __nv_bfloat16 g_wqkvex[(size_t)NQKV * 2 * HIDD];
__device__ float         g_bqkv  [NQKV];
__device__ __nv_bfloat16 g_woex  [(size_t)HIDD * 2 * HIDD];
__device__ float         g_qkv   [(size_t)TT * NQKV];
__device__ __nv_bfloat16 g_qex   [(size_t)NHQ * TT * 2 * HDIM];   // pre-scaled by SCALE_L2E
__device__ __nv_bfloat16 g_kex   [(size_t)NKVH * TT * 2 * HDIM];
__device__ __nv_bfloat16 g_vex   [(size_t)NKVH * HDIM * 2 * TT];  // V^T [4][128][hi|lo]
__device__ __nv_bfloat16 g_attnex[(size_t)TT * 2 * HIDD];
__device__ float         g_rtab  [(size_t)TT * 128];              // [t][cos(64)|sin(64)]

// ------------------------- helpers ------------------------------------------
__device__ __forceinline__ void split2(float x, __nv_bfloat16& h, __nv_bfloat16& l) {
    h = __float2bfloat16(x);
    l = __float2bfloat16(x - __bfloat162float(h));
}

__device__ __forceinline__ uint32_t smem_u32(const void* p) {
    uint32_t a;
    asm("{ .reg .u64 t; cvta.to.shared.u64 t, %1; cvt.u32.u64 %0, t; }" : "=r"(a) : "l"(p));
    return a;
}

__device__ __forceinline__ void cp16(uint32_t dst, const void* src) {
    asm volatile("cp.async.cg.shared.global [%0], [%1], 16;" :: "r"(dst), "l"(src));
}

__device__ __forceinline__ float ex2(float x) {
    float y;
    asm("ex2.approx.ftz.f32 %0, %1;" : "=f"(y) : "f"(x));
    return y;
}

__device__ __forceinline__ void redadd(float* p, float v) {
    asm volatile("red.global.add.f32 [%0], %1;" :: "l"(p), "f"(v) : "memory");
}

__device__ __forceinline__ void hmma(float* c, const uint32_t* a, const uint32_t* b) {
    asm volatile(
        "mma.sync.aligned.m16n8k16.row.col.f32.bf16.bf16.f32 "
        "{%0,%1,%2,%3}, {%4,%5,%6,%7}, {%8,%9}, {%0,%1,%2,%3};"
        : "+f"(c[0]), "+f"(c[1]), "+f"(c[2]), "+f"(c[3])
        : "r"(a[0]), "r"(a[1]), "r"(a[2]), "r"(a[3]), "r"(b[0]), "r"(b[1]));
}

__device__ __forceinline__ void ldx4(uint32_t* r, uint32_t addr) {
    asm volatile("ldmatrix.sync.aligned.m8n8.x4.shared.b16 {%0,%1,%2,%3}, [%4];"
                 : "=r"(r[0]), "=r"(r[1]), "=r"(r[2]), "=r"(r[3]) : "r"(addr));
}

__device__ __forceinline__ uint32_t packbf(float a, float b) {
    __nv_bfloat162 v = __floats2bfloat162_rn(a, b);
    return *reinterpret_cast<uint32_t*>(&v);
}

__device__ __forceinline__ void packsplit(float a, float b, uint32_t& hi, uint32_t& lo) {
    __nv_bfloat16 ha = __float2bfloat16(a), hb = __float2bfloat16(b);
    float la = a - __bfloat162float(ha);
    float lb = b - __bfloat162float(hb);
    __nv_bfloat162 hv; hv.x = ha; hv.y = hb;
    hi = *reinterpret_cast<uint32_t*>(&hv);
    lo = packbf(la, lb);
}

// ------------------------- HMMA split-bf16 GEMM ------------------------------
// SPLITK=false: full K, standard fp32 store epilogue (+bias, alpha).
// SPLITK=true : blockIdx.z in [0,2) handles half the K chunks; epilogue does
//               red.global.add.f32 into zero-initialized C (no bias, alpha=1).
#define APAD   40
#define STAGES 4

template <bool SPLITK>
__global__ __launch_bounds__(256, 2) void mma_gemm(
    const __nv_bfloat16* __restrict__ A,
    const __nv_bfloat16* __restrict__ B,
    const float* __restrict__ bias,
    float* __restrict__ C, int ldc,
    int Khalf, float alpha)
{
    constexpr int MI     = 4;
    constexpr int ACP    = 2;
    constexpr int ABYTES = 128 * APAD * 2;
    constexpr int BBYTES = 128 * APAD * 2;

    extern __shared__ char sm[];
    const uint32_t sA = smem_u32(sm);
    const uint32_t sB = sA + STAGES * ABYTES;

    const int t   = threadIdx.x;
    const int wid = t >> 5, lid = t & 31;
    const int wm  = wid >> 2;
    const int wn  = wid & 3;
    const long lda = 2L * Khalf;
    const int m0 = blockIdx.y * 128, n0 = blockIdx.x * 128;

    A += (long)m0 * lda;
    B += (long)n0 * lda;

    const int a_row = (lid & 7) + ((lid >> 3) & 1) * 8;
    const int a_c8  = (lid >> 4) * 8;
    const int b4r = (lid & 7) + ((lid >> 4) & 1) * 8;
    const int b4c = ((lid >> 3) & 1) * 8;
    const uint32_t aBase  = sA + ((wm * 64 + a_row) * APAD + a_c8) * 2;
    const uint32_t bBase4 = sB + ((wn * 32 + b4r) * APAD + b4c) * 2;

    const int nk  = Khalf >> 5;
    const int nk3 = 3 * nk;
    int c0 = 0, c1 = nk3;
    if (SPLITK) {
        const int half = nk3 >> 1;
        c0 = blockIdx.z * half;
        c1 = c0 + half;
    }

    float acc[MI][4][4];
#pragma unroll
    for (int i = 0; i < MI; i++)
#pragma unroll
        for (int j = 0; j < 4; j++)
#pragma unroll
            for (int r = 0; r < 4; r++) acc[i][j][r] = 0.0f;

    auto issue = [&](int c) {
        int r  = c / nk;
        int kk = c - r * nk;
        long ao = (long)((r == 1) ? Khalf : 0) + (long)kk * 32;
        long bo = (long)((r == 2) ? Khalf : 0) + (long)kk * 32;
        uint32_t stA = (uint32_t)(c & (STAGES - 1)) * ABYTES;
        uint32_t stB = (uint32_t)(c & (STAGES - 1)) * BBYTES;
#pragma unroll
        for (int i = 0; i < ACP; i++) {
            int idx = t + i * 256, row = idx >> 2, q = (idx & 3) * 8;
            cp16(sA + stA + (row * APAD + q) * 2, A + (long)row * lda + ao + q);
        }
#pragma unroll
        for (int i = 0; i < 2; i++) {
            int idx = t + i * 256, row = idx >> 2, q = (idx & 3) * 8;
            cp16(sB + stB + (row * APAD + q) * 2, B + (long)row * lda + bo + q);
        }
    };

#pragma unroll
    for (int s = 0; s < STAGES - 1; s++) {
        issue(c0 + s);
        asm volatile("cp.async.commit_group;" ::: "memory");
    }

    for (int c = c0; c < c1; c++) {
        asm volatile("cp.async.wait_group %0;" :: "n"(STAGES - 2) : "memory");
        __syncthreads();

        const uint32_t stA = (uint32_t)(c & (STAGES - 1)) * ABYTES;
        const uint32_t stB = (uint32_t)(c & (STAGES - 1)) * BBYTES;
#pragma unroll
        for (int ks = 0; ks < 2; ks++) {
            uint32_t af[MI][4], bf[2][4];
#pragma unroll
            for (int mi = 0; mi < MI; mi++)
                ldx4(af[mi], aBase + stA + (mi * 16 * APAD + ks * 16) * 2);
#pragma unroll
            for (int njp = 0; njp < 2; njp++)
                ldx4(bf[njp], bBase4 + stB + (njp * 16 * APAD + ks * 16) * 2);
#pragma unroll
            for (int mi = 0; mi < MI; mi++)
#pragma unroll
                for (int njp = 0; njp < 2; njp++) {
                    hmma(acc[mi][2 * njp],     af[mi], bf[njp]);
                    hmma(acc[mi][2 * njp + 1], af[mi], bf[njp] + 2);
                }
        }
        if (c + STAGES - 1 < c1) issue(c + STAGES - 1);
        asm volatile("cp.async.commit_group;" ::: "memory");
    }

    const int er = lid >> 2;
    const int ec = (lid & 3) * 2;
#pragma unroll
    for (int nj = 0; nj < 4; nj++) {
        int col = n0 + wn * 32 + nj * 8 + ec;
        float b0 = 0.f, b1 = 0.f;
        if (!SPLITK && bias) { b0 = __ldg(bias + col); b1 = __ldg(bias + col + 1); }
#pragma unroll
        for (int mi = 0; mi < MI; mi++) {
            int row0 = m0 + wm * 64 + mi * 16 + er;
            if (SPLITK) {
                float* p0 = C + (long)row0 * ldc + col;
                float* p1 = C + (long)(row0 + 8) * ldc + col;
                redadd(p0,     acc[mi][nj][0]);
                redadd(p0 + 1, acc[mi][nj][1]);
                redadd(p1,     acc[mi][nj][2]);
                redadd(p1 + 1, acc[mi][nj][3]);
            } else {
                float2 v0 = { alpha * acc[mi][nj][0] + b0, alpha * acc[mi][nj][1] + b1 };
                float2 v1 = { alpha * acc[mi][nj][2] + b0, alpha * acc[mi][nj][3] + b1 };
                *(float2*)(C + (long)row0 * ldc + col)       = v0;
                *(float2*)(C + (long)(row0 + 8) * ldc + col) = v1;
            }
        }
    }
}

// ------------------------- fused flash attention -----------------------------
#define KPAD 264
#define VPAD 136
#define FSM_BYTES ((128 * KPAD * 2 + 128 * VPAD * 2) * 2)   // 204800
#define NCHUNK (TT / 128)

__global__ __launch_bounds__(256, 1) void flash_attn(
    const __nv_bfloat16* __restrict__ Qe,
    const __nv_bfloat16* __restrict__ Ke,
    const __nv_bfloat16* __restrict__ Ve,
    __nv_bfloat16* __restrict__ Oex)
{
    extern __shared__ char fsm[];
    const uint32_t uQ  = smem_u32(fsm);
    const uint32_t uK  = uQ + 128 * KPAD * 2;
    const uint32_t uVh = uK + 128 * KPAD * 2;
    const uint32_t uVl = uVh + 128 * VPAD * 2;

    const int t = threadIdx.x, wid = t >> 5, lid = t & 31;
    const int h = blockIdx.y, hk = h / GQA;
    const int q0 = blockIdx.x * 128;

    const __nv_bfloat16* Qg = Qe + ((long)h * TT + q0) * 256;
    const __nv_bfloat16* Kg = Ke + (long)hk * TT * 256;
    const __nv_bfloat16* Vg = Ve + (long)hk * HDIM * (2 * TT);

    auto loadK = [&](int kc) {
        const __nv_bfloat16* src = Kg + (long)kc * 128 * 256;
#pragma unroll
        for (int i = 0; i < 16; i++) {
            int idx = t + i * 256, row = idx >> 5, ce = (idx & 31) * 8;
            cp16(uK + (row * KPAD + ce) * 2, src + (long)row * 256 + ce);
        }
    };
    auto loadV = [&](int kc) {
#pragma unroll
        for (int i = 0; i < 8; i++) {
            int idx = t + i * 256, row = idx >> 4, ce = (idx & 15) * 8;
            const __nv_bfloat16* s = Vg + (long)row * (2 * TT) + kc * 128 + ce;
            cp16(uVh + (row * VPAD + ce) * 2, s);
            cp16(uVl + (row * VPAD + ce) * 2, s + TT);
        }
    };

#pragma unroll
    for (int i = 0; i < 16; i++) {
        int idx = t + i * 256, row = idx >> 5, ce = (idx & 31) * 8;
        cp16(uQ + (row * KPAD + ce) * 2, Qg + (long)row * 256 + ce);
    }
    loadK(0);
    loadV(0);
    asm volatile("cp.async.commit_group;" ::: "memory");
    asm volatile("cp.async.wait_group 0;" ::: "memory");
    __syncthreads();

    const int a_row = (lid & 7) + ((lid >> 3) & 1) * 8;
    const int a_c8  = (lid >> 4) * 8;
    const int b4r   = (lid & 7) + ((lid >> 4) & 1) * 8;
    const int b4c   = ((lid >> 3) & 1) * 8;
    const uint32_t aQbase = uQ + ((wid * 16 + a_row) * KPAD + a_c8) * 2;

    float oacc[16][4];
#pragma unroll
    for (int nj = 0; nj < 16; nj++)
#pragma unroll
        for (int r = 0; r < 4; r++) oacc[nj][r] = 0.0f;
    float m0 = -1e30f, m1 = -1e30f, l0 = 0.0f, l1 = 0.0f;

    for (int kc = 0; kc < NCHUNK; kc++) {
        if (kc > 0) {
            asm volatile("cp.async.wait_group 1;" ::: "memory");
            __syncthreads();
        }

        float sacc[16][4];
#pragma unroll
        for (int nj = 0; nj < 16; nj++)
#pragma unroll
            for (int r = 0; r < 4; r++) sacc[nj][r] = 0.0f;

#pragma unroll
        for (int ks = 0; ks < 8; ks++) {
            uint32_t aqh[4], aql[4];
            ldx4(aqh, aQbase + (ks * 16) * 2);
            ldx4(aql, aQbase + (128 + ks * 16) * 2);
#pragma unroll
            for (int njp = 0; njp < 8; njp++) {
                uint32_t bh[4], bl[4];
                ldx4(bh, uK + ((njp * 16 + b4r) * KPAD + ks * 16 + b4c) * 2);
                ldx4(bl, uK + ((njp * 16 + b4r) * KPAD + 128 + ks * 16 + b4c) * 2);
                hmma(sacc[2 * njp],     aqh, bh);
                hmma(sacc[2 * njp],     aql, bh);
                hmma(sacc[2 * njp],     aqh, bl);
                hmma(sacc[2 * njp + 1], aqh, bh + 2);
                hmma(sacc[2 * njp + 1], aql, bh + 2);
                hmma(sacc[2 * njp + 1], aqh, bl + 2);
            }
        }
        __syncthreads();
        if (kc + 1 < NCHUNK) {
            loadK(kc + 1);
            asm volatile("cp.async.commit_group;" ::: "memory");
        }

        float mx0 = -1e30f, mx1 = -1e30f;
#pragma unroll
        for (int nj = 0; nj < 16; nj++) {
            mx0 = fmaxf(mx0, fmaxf(sacc[nj][0], sacc[nj][1]));
            mx1 = fmaxf(mx1, fmaxf(sacc[nj][2], sacc[nj][3]));
        }
        mx0 = fmaxf(mx0, __shfl_xor_sync(0xffffffffu, mx0, 1));
        mx0 = fmaxf(mx0, __shfl_xor_sync(0xffffffffu, mx0, 2));
        mx1 = fmaxf(mx1, __shfl_xor_sync(0xffffffffu, mx1, 1));
        mx1 = fmaxf(mx1, __shfl_xor_sync(0xffffffffu, mx1, 2));
        float nm0 = fmaxf(m0, mx0), nm1 = fmaxf(m1, mx1);
        float sc0 = ex2(m0 - nm0), sc1 = ex2(m1 - nm1);
        m0 = nm0; m1 = nm1;
        l0 *= sc0; l1 *= sc1;
#pragma unroll
        for (int nj = 0; nj < 16; nj++) {
            oacc[nj][0] *= sc0; oacc[nj][1] *= sc0;
            oacc[nj][2] *= sc1; oacc[nj][3] *= sc1;
        }

        if (kc + 1 < NCHUNK) {
            asm volatile("cp.async.wait_group 1;" ::: "memory");
        } else {
            asm volatile("cp.async.wait_group 0;" ::: "memory");
        }
        __syncthreads();

#pragma unroll
        for (int ks = 0; ks < 8; ks++) {
            float e00 = ex2(sacc[2 * ks][0]     - m0);
            float e01 = ex2(sacc[2 * ks][1]     - m0);
            float e02 = ex2(sacc[2 * ks][2]     - m1);
            float e03 = ex2(sacc[2 * ks][3]     - m1);
            float e10 = ex2(sacc[2 * ks + 1][0] - m0);
            float e11 = ex2(sacc[2 * ks + 1][1] - m0);
            float e12 = ex2(sacc[2 * ks + 1][2] - m1);
            float e13 = ex2(sacc[2 * ks + 1][3] - m1);
            l0 += e00 + e01 + e10 + e11;
            l1 += e02 + e03 + e12 + e13;
            uint32_t ph[4], pl[4];
            packsplit(e00, e01, ph[0], pl[0]);
            packsplit(e02, e03, ph[1], pl[1]);
            packsplit(e10, e11, ph[2], pl[2]);
            packsplit(e12, e13, ph[3], pl[3]);
#pragma unroll
            for (int njp = 0; njp < 8; njp++) {
                uint32_t bvh[4], bvl[4];
                ldx4(bvh, uVh + ((njp * 16 + b4r) * VPAD + ks * 16 + b4c) * 2);
                ldx4(bvl, uVl + ((njp * 16 + b4r) * VPAD + ks * 16 + b4c) * 2);
                hmma(oacc[2 * njp],     ph, bvh);
                hmma(oacc[2 * njp],     pl, bvh);
                hmma(oacc[2 * njp],     ph, bvl);
                hmma(oacc[2 * njp + 1], ph, bvh + 2);
                hmma(oacc[2 * njp + 1], pl, bvh + 2);
                hmma(oacc[2 * njp + 1], ph, bvl + 2);
            }
        }
        __syncthreads();
        if (kc + 1 < NCHUNK) {
            loadV(kc + 1);
            asm volatile("cp.async.commit_group;" ::: "memory");
        }
    }

    l0 += __shfl_xor_sync(0xffffffffu, l0, 1);
    l0 += __shfl_xor_sync(0xffffffffu, l0, 2);
    l1 += __shfl_xor_sync(0xffffffffu, l1, 1);
    l1 += __shfl_xor_sync(0xffffffffu, l1, 2);
    const float inv0 = 1.0f / l0, inv1 = 1.0f / l1;

    const int gr = lid >> 2;
    const int ec = (lid & 3) * 2;
    const long r0 = q0 + wid * 16 + gr;
    const long r1 = r0 + 8;
#pragma unroll
    for (int nj = 0; nj < 16; nj++) {
        int col = h * HDIM + nj * 8 + ec;
        uint32_t hi, lo;
        packsplit(oacc[nj][0] * inv0, oacc[nj][1] * inv0, hi, lo);
        *(uint32_t*)(Oex + r0 * (2 * HIDD) + col)        = hi;
        *(uint32_t*)(Oex + r0 * (2 * HIDD) + HIDD + col) = lo;
        packsplit(oacc[nj][2] * inv1, oacc[nj][3] * inv1, hi, lo);
        *(uint32_t*)(Oex + r1 * (2 * HIDD) + col)        = hi;
        *(uint32_t*)(Oex + r1 * (2 * HIDD) + HIDD + col) = lo;
    }
}

// ------------------------- conversion kernels -------------------------------
__global__ void zero_out(float4* __restrict__ p, long n4)
{
    long i = (long)blockIdx.x * 256 + threadIdx.x;
    if (i < n4) p[i] = make_float4(0.f, 0.f, 0.f, 0.f);
}

__global__ void split_rows(const float* __restrict__ in, __nv_bfloat16* __restrict__ out,
                           int K)
{
    const int r = blockIdx.y;
    const int k = (blockIdx.x * 256 + threadIdx.x) * 4;
    if (k >= K) return;
    float4 x = *(const float4*)(in + (long)r * K + k);
    __nv_bfloat16 h0,l0,h1,l1,h2,l2,h3,l3;
    split2(x.x,h0,l0); split2(x.y,h1,l1); split2(x.z,h2,l2); split2(x.w,h3,l3);
    __nv_bfloat16* oh = out + (long)r * 2 * K + k;
    oh[0]=h0; oh[1]=h1; oh[2]=h2; oh[3]=h3;
    __nv_bfloat16* ol = oh + K;
    ol[0]=l0; ol[1]=l1; ol[2]=l2; ol[3]=l3;
}

// generic 64x64 transpose-split (used for V)
__global__ void split_transpose(const float* __restrict__ in, int ldin, long inBatch,
                                __nv_bfloat16* __restrict__ out, int Kdim, long outBatch)
{
    __shared__ float smt[64][65];
    const float* ip = in + (long)blockIdx.z * inBatch;
    __nv_bfloat16* op = out + (long)blockIdx.z * outBatch;
    const int k0 = blockIdx.x * 64, n0 = blockIdx.y * 64;
    const int tx = threadIdx.x, ty = threadIdx.y;

#pragma unroll
    for (int rr = 0; rr < 8; rr++) {
        int i = ty + rr * 8;
        float2 v = *(const float2*)(ip + (long)(k0 + i) * ldin + n0 + tx * 2);
        smt[i][tx * 2]     = v.x;
        smt[i][tx * 2 + 1] = v.y;
    }
    __syncthreads();

#pragma unroll
    for (int rr = 0; rr < 8; rr++) {
        int j = ty + rr * 8;
        float x0 = smt[tx * 2][j];
        float x1 = smt[tx * 2 + 1][j];
        uint32_t hi, lo;
        packsplit(x0, x1, hi, lo);
        long base = (long)(n0 + j) * (2L * Kdim) + k0 + tx * 2;
        *(uint32_t*)(op + base)        = hi;
        *(uint32_t*)(op + base + Kdim) = lo;
    }
}

// merged weight transpose-split: one launch for wq|wk|wv|wo.
__global__ void split_transpose_w(const float* __restrict__ wq, const float* __restrict__ wk,
                                  const float* __restrict__ wv, const float* __restrict__ wo,
                                  __nv_bfloat16* __restrict__ wqkvex,
                                  __nv_bfloat16* __restrict__ woex)
{
    __shared__ float smt[64][65];
    int yb = blockIdx.y;
    const float* src; int ldin; __nv_bfloat16* dst;
    if (yb < 56)       { src = wq; ldin = HIDD; dst = wqkvex; }
    else if (yb < 64)  { src = wk; ldin = 512;  dst = wqkvex + (size_t)HIDD * 2 * HIDD;        yb -= 56; }
    else if (yb < 72)  { src = wv; ldin = 512;  dst = wqkvex + (size_t)(HIDD + 512) * 2 * HIDD; yb -= 64; }
    else               { src = wo; ldin = HIDD; dst = woex;                                     yb -= 72; }

    const int k0 = blockIdx.x * 64, n0 = yb * 64;
    const int tx = threadIdx.x, ty = threadIdx.y;

#pragma unroll
    for (int rr = 0; rr < 8; rr++) {
        int i = ty + rr * 8;
        float2 v = *(const float2*)(src + (long)(k0 + i) * ldin + n0 + tx * 2);
        smt[i][tx * 2]     = v.x;
        smt[i][tx * 2 + 1] = v.y;
    }
    __syncthreads();

#pragma unroll
    for (int rr = 0; rr < 8; rr++) {
        int j = ty + rr * 8;
        float x0 = smt[tx * 2][j];
        float x1 = smt[tx * 2 + 1][j];
        uint32_t hi, lo;
        packsplit(x0, x1, hi, lo);
        long base = (long)(n0 + j) * (2L * HIDD) + k0 + tx * 2;
        *(uint32_t*)(dst + base)        = hi;
        *(uint32_t*)(dst + base + HIDD) = lo;
    }
}

__global__ void rope_tab(const int* __restrict__ pos, float* __restrict__ tab)
{
    int t = blockIdx.x, d = threadIdx.x;
    float p = (float)pos[t];
    float ang = p * exp2f(-(float)d * (LOG2_THETA / 64.0f));
    float s, c;
    sincosf(ang, &s, &c);
    tab[t * 128 + d]      = c;
    tab[t * 128 + 64 + d] = s;
}

// merged RoPE + scale + split for Q and K. grid (TT/4, 32): y<28 -> Q head, else K head.
__global__ void rope_split(const float* __restrict__ qkv,
                           const float* __restrict__ tab,
                           __nv_bfloat16* __restrict__ qex,
                           __nv_bfloat16* __restrict__ kex)
{
    int d   = threadIdx.x & 63;
    int sub = threadIdx.x >> 6;
    int t   = blockIdx.x * 4 + sub;
    int h   = blockIdx.y;
    const float* row;
    __nv_bfloat16* o;
    float scale;
    if (h < NHQ) {
        row = qkv + (long)t * NQKV + h * HDIM;
        o   = qex + ((long)h * TT + t) * (2 * HDIM);
        scale = SCALE_L2E;
    } else {
        int hk = h - NHQ;
        row = qkv + (long)t * NQKV + HIDD + hk * HDIM;
        o   = kex + ((long)hk * TT + t) * (2 * HDIM);
        scale = 1.0f;
    }
    float c = tab[t * 128 + d];
    float s = tab[t * 128 + 64 + d];
    float x1 = row[d], x2 = row[d + 64];
    float y1 = (x1 * c - x2 * s) * scale;
    float y2 = (x2 * c + x1 * s) * scale;
    __nv_bfloat16 h1, l1, h2, l2;
    split2(y1, h1, l1); split2(y2, h2, l2);
    o[d] = h1; o[d + 64] = h2;
    o[128 + d] = l1; o[128 + d + 64] = l2;
}

__global__ void concat_bias(const float* __restrict__ bq, const float* __restrict__ bk,
                            const float* __restrict__ bv, float* __restrict__ o)
{
    int i = blockIdx.x * 256 + threadIdx.x;
    if (i >= NQKV) return;
    if (i < HIDD)            o[i] = bq[i];
    else if (i < HIDD + 512) o[i] = bk[i - HIDD];
    else                     o[i] = bv[i - HIDD - 512];
}

// ------------------------- launch -------------------------------------------
extern "C" void kernel_launch(void* const* d_in, const int* in_sizes, int n_in,
                              void* d_out, int out_size)
{
    const int*   pos = (const int*)d_in[0];
    const float* hs  = (const float*)d_in[1];
    const float* wq  = (const float*)d_in[2];
    const float* bq  = (const float*)d_in[3];
    const float* wk  = (const float*)d_in[4];
    const float* bk  = (const float*)d_in[5];
    const float* wv  = (const float*)d_in[6];
    const float* bv  = (const float*)d_in[7];
    const float* wo  = (const float*)d_in[8];
    float* out = (float*)d_out;

    __nv_bfloat16 *hsex, *wqkvex, *woex, *qex, *kex, *vex, *attnex;
    float *qkv, *bqkv, *rtab;
    cudaGetSymbolAddress((void**)&hsex,   g_hsex);
    cudaGetSymbolAddress((void**)&wqkvex, g_wqkvex);
    cudaGetSymbolAddress((void**)&bqkv,   g_bqkv);
    cudaGetSymbolAddress((void**)&woex,   g_woex);
    cudaGetSymbolAddress((void**)&qkv,    g_qkv);
    cudaGetSymbolAddress((void**)&qex,    g_qex);
    cudaGetSymbolAddress((void**)&kex,    g_kex);
    cudaGetSymbolAddress((void**)&vex,    g_vex);
    cudaGetSymbolAddress((void**)&attnex, g_attnex);
    cudaGetSymbolAddress((void**)&rtab,   g_rtab);

    const int smem128 = STAGES * (128 + 128) * APAD * 2;
    cudaFuncSetAttribute(mma_gemm<false>, cudaFuncAttributeMaxDynamicSharedMemorySize, smem128);
    cudaFuncSetAttribute(mma_gemm<true>,  cudaFuncAttributeMaxDynamicSharedMemorySize, smem128);
    cudaFuncSetAttribute(flash_attn,      cudaFuncAttributeMaxDynamicSharedMemorySize, FSM_BYTES);

    // ---- zero-init output (consumed by split-K red.add epilogue) ----
    {
        long n4 = (long)TT * HIDD / 4;
        zero_out<<<(unsigned)((n4 + 255) / 256), 256>>>((float4*)out, n4);
    }

    // ---- operand conversions (merged launches) ----
    split_rows<<<dim3((HIDD/4 + 255) / 256, TT), 256>>>(hs, hsex, HIDD);
    split_transpose_w<<<dim3(HIDD/64, 128), dim3(32,8)>>>(wq, wk, wv, wo, wqkvex, woex);
    concat_bias<<<(NQKV + 255) / 256, 256>>>(bq, bk, bv, bqkv);
    rope_tab<<<TT, 64>>>(pos, rtab);

    // ---- fused QKV projection ----
    mma_gemm<false><<<dim3(NQKV/128, TT/128, 1), 256, smem128>>>(
        hsex, wqkvex, bqkv, qkv, NQKV, HIDD, 1.0f);

    // ---- RoPE (Q scaled) + split; V transpose + split ----
    rope_split<<<dim3(TT/4, NHQ + NKVH), 256>>>(qkv, rtab, qex, kex);
    split_transpose<<<dim3(TT/64, HDIM/64, NKVH), dim3(32,8)>>>(
        qkv + HIDD + 512, NQKV, (long)HDIM, vex, TT, (long)HDIM * 2 * TT);

    // ---- fused attention ----
    flash_attn<<<dim3(TT/128, NHQ), 256, FSM_BYTES>>>(qex, kex, vex, attnex);

    // ---- out = attn @ wo  (split-K=2: 896 blocks = 3.03 full waves) ----
    mma_gemm<true><<<dim3(HIDD/128, TT/128, 2), 256, smem128>>>(
        attnex, woex, nullptr, out, HIDD, HIDD, 1.0f);
}

// round 16
// speedup vs baseline: 1.0219x; 1.0042x over previous
#include <cuda_runtime.h>
#include <cuda_bf16.h>
#include <cstdint>

#define TT    2048
#define HIDD  3584
#define NHQ   28
#define NKVH  4
#define HDIM  128
#define GQA   7
#define NQKV  4608
#define ASCALE 0.08838834764831845f
#define SCALE_L2E 0.12751743f          // ASCALE * log2(e)
#define LOG2_THETA 19.931568569324174f

// ------------------------- static device scratch ----------------------------
__device__ __nv_bfloat16 g_hsex  [(size_t)TT * 2 * HIDD];
__device__ __nv_bfloat16 g_wqkvex[(size_t)NQKV * 2 * HIDD];
__device__ float         g_bqkv  [NQKV];
__device__ __nv_bfloat16 g_woex  [(size_t)HIDD * 2 * HIDD];
__device__ float         g_qkv   [(size_t)TT * NQKV];
__device__ __nv_bfloat16 g_qex   [(size_t)NHQ * TT * 2 * HDIM];   // pre-scaled by SCALE_L2E
__device__ __nv_bfloat16 g_kex   [(size_t)NKVH * TT * 2 * HDIM];
__device__ __nv_bfloat16 g_vex   [(size_t)NKVH * HDIM * 2 * TT];  // V^T [4][128][hi|lo]
__device__ __nv_bfloat16 g_attnex[(size_t)TT * 2 * HIDD];
__device__ float         g_rtab  [(size_t)TT * 128];              // [t][cos(64)|sin(64)]

// ------------------------- helpers ------------------------------------------
__device__ __forceinline__ void split2(float x, __nv_bfloat16& h, __nv_bfloat16& l) {
    h = __float2bfloat16(x);
    l = __float2bfloat16(x - __bfloat162float(h));
}

__device__ __forceinline__ uint32_t smem_u32(const void* p) {
    uint32_t a;
    asm("{ .reg .u64 t; cvta.to.shared.u64 t, %1; cvt.u32.u64 %0, t; }" : "=r"(a) : "l"(p));
    return a;
}

__device__ __forceinline__ void cp16(uint32_t dst, const void* src) {
    asm volatile("cp.async.cg.shared.global [%0], [%1], 16;" :: "r"(dst), "l"(src));
}

__device__ __forceinline__ float ex2(float x) {
    float y;
    asm("ex2.approx.ftz.f32 %0, %1;" : "=f"(y) : "f"(x));
    return y;
}

__device__ __forceinline__ void redadd(float* p, float v) {
    asm volatile("red.global.add.f32 [%0], %1;" :: "l"(p), "f"(v) : "memory");
}

__device__ __forceinline__ void hmma(float* c, const uint32_t* a, const uint32_t* b) {
    asm volatile(
        "mma.sync.aligned.m16n8k16.row.col.f32.bf16.bf16.f32 "
        "{%0,%1,%2,%3}, {%4,%5,%6,%7}, {%8,%9}, {%0,%1,%2,%3};"
        : "+f"(c[0]), "+f"(c[1]), "+f"(c[2]), "+f"(c[3])
        : "r"(a[0]), "r"(a[1]), "r"(a[2]), "r"(a[3]), "r"(b[0]), "r"(b[1]));
}

__device__ __forceinline__ void ldx4(uint32_t* r, uint32_t addr) {
    asm volatile("ldmatrix.sync.aligned.m8n8.x4.shared.b16 {%0,%1,%2,%3}, [%4];"
                 : "=r"(r[0]), "=r"(r[1]), "=r"(r[2]), "=r"(r[3]) : "r"(addr));
}

__device__ __forceinline__ uint32_t packbf(float a, float b) {
    __nv_bfloat162 v = __floats2bfloat162_rn(a, b);
    return *reinterpret_cast<uint32_t*>(&v);
}

__device__ __forceinline__ void packsplit(float a, float b, uint32_t& hi, uint32_t& lo) {
    __nv_bfloat16 ha = __float2bfloat16(a), hb = __float2bfloat16(b);
    float la = a - __bfloat162float(ha);
    float lb = b - __bfloat162float(hb);
    __nv_bfloat162 hv; hv.x = ha; hv.y = hb;
    hi = *reinterpret_cast<uint32_t*>(&hv);
    lo = packbf(la, lb);
}

// ------------------------- HMMA split-bf16 GEMM ------------------------------
#define APAD   40
#define STAGES 4

template <bool SPLITK>
__global__ __launch_bounds__(256, 2) void mma_gemm(
    const __nv_bfloat16* __restrict__ A,
    const __nv_bfloat16* __restrict__ B,
    const float* __restrict__ bias,
    float* __restrict__ C, int ldc,
    int Khalf, float alpha)
{
    constexpr int MI     = 4;
    constexpr int ACP    = 2;
    constexpr int ABYTES = 128 * APAD * 2;
    constexpr int BBYTES = 128 * APAD * 2;

    extern __shared__ char sm[];
    const uint32_t sA = smem_u32(sm);
    const uint32_t sB = sA + STAGES * ABYTES;

    const int t   = threadIdx.x;
    const int wid = t >> 5, lid = t & 31;
    const int wm  = wid >> 2;
    const int wn  = wid & 3;
    const long lda = 2L * Khalf;
    const int m0 = blockIdx.y * 128, n0 = blockIdx.x * 128;

    A += (long)m0 * lda;
    B += (long)n0 * lda;

    const int a_row = (lid & 7) + ((lid >> 3) & 1) * 8;
    const int a_c8  = (lid >> 4) * 8;
    const int b4r = (lid & 7) + ((lid >> 4) & 1) * 8;
    const int b4c = ((lid >> 3) & 1) * 8;
    const uint32_t aBase  = sA + ((wm * 64 + a_row) * APAD + a_c8) * 2;
    const uint32_t bBase4 = sB + ((wn * 32 + b4r) * APAD + b4c) * 2;

    const int nk  = Khalf >> 5;
    const int nk3 = 3 * nk;
    int c0 = 0, c1 = nk3;
    if (SPLITK) {
        const int half = nk3 >> 1;
        c0 = blockIdx.z * half;
        c1 = c0 + half;
    }

    float acc[MI][4][4];
#pragma unroll
    for (int i = 0; i < MI; i++)
#pragma unroll
        for (int j = 0; j < 4; j++)
#pragma unroll
            for (int r = 0; r < 4; r++) acc[i][j][r] = 0.0f;

    auto issue = [&](int c) {
        int r  = c / nk;
        int kk = c - r * nk;
        long ao = (long)((r == 1) ? Khalf : 0) + (long)kk * 32;
        long bo = (long)((r == 2) ? Khalf : 0) + (long)kk * 32;
        uint32_t stA = (uint32_t)(c & (STAGES - 1)) * ABYTES;
        uint32_t stB = (uint32_t)(c & (STAGES - 1)) * BBYTES;
#pragma unroll
        for (int i = 0; i < ACP; i++) {
            int idx = t + i * 256, row = idx >> 2, q = (idx & 3) * 8;
            cp16(sA + stA + (row * APAD + q) * 2, A + (long)row * lda + ao + q);
        }
#pragma unroll
        for (int i = 0; i < 2; i++) {
            int idx = t + i * 256, row = idx >> 2, q = (idx & 3) * 8;
            cp16(sB + stB + (row * APAD + q) * 2, B + (long)row * lda + bo + q);
        }
    };

#pragma unroll
    for (int s = 0; s < STAGES - 1; s++) {
        issue(c0 + s);
        asm volatile("cp.async.commit_group;" ::: "memory");
    }

    for (int c = c0; c < c1; c++) {
        asm volatile("cp.async.wait_group %0;" :: "n"(STAGES - 2) : "memory");
        __syncthreads();

        const uint32_t stA = (uint32_t)(c & (STAGES - 1)) * ABYTES;
        const uint32_t stB = (uint32_t)(c & (STAGES - 1)) * BBYTES;
#pragma unroll
        for (int ks = 0; ks < 2; ks++) {
            uint32_t af[MI][4], bf[2][4];
#pragma unroll
            for (int mi = 0; mi < MI; mi++)
                ldx4(af[mi], aBase + stA + (mi * 16 * APAD + ks * 16) * 2);
#pragma unroll
            for (int njp = 0; njp < 2; njp++)
                ldx4(bf[njp], bBase4 + stB + (njp * 16 * APAD + ks * 16) * 2);
#pragma unroll
            for (int mi = 0; mi < MI; mi++)
#pragma unroll
                for (int njp = 0; njp < 2; njp++) {
                    hmma(acc[mi][2 * njp],     af[mi], bf[njp]);
                    hmma(acc[mi][2 * njp + 1], af[mi], bf[njp] + 2);
                }
        }
        if (c + STAGES - 1 < c1) issue(c + STAGES - 1);
        asm volatile("cp.async.commit_group;" ::: "memory");
    }

    const int er = lid >> 2;
    const int ec = (lid & 3) * 2;
#pragma unroll
    for (int nj = 0; nj < 4; nj++) {
        int col = n0 + wn * 32 + nj * 8 + ec;
        float b0 = 0.f, b1 = 0.f;
        if (!SPLITK && bias) { b0 = __ldg(bias + col); b1 = __ldg(bias + col + 1); }
#pragma unroll
        for (int mi = 0; mi < MI; mi++) {
            int row0 = m0 + wm * 64 + mi * 16 + er;
            if (SPLITK) {
                float* p0 = C + (long)row0 * ldc + col;
                float* p1 = C + (long)(row0 + 8) * ldc + col;
                redadd(p0,     acc[mi][nj][0]);
                redadd(p0 + 1, acc[mi][nj][1]);
                redadd(p1,     acc[mi][nj][2]);
                redadd(p1 + 1, acc[mi][nj][3]);
            } else {
                float2 v0 = { alpha * acc[mi][nj][0] + b0, alpha * acc[mi][nj][1] + b1 };
                float2 v1 = { alpha * acc[mi][nj][2] + b0, alpha * acc[mi][nj][3] + b1 };
                *(float2*)(C + (long)row0 * ldc + col)       = v0;
                *(float2*)(C + (long)(row0 + 8) * ldc + col) = v1;
            }
        }
    }
}

// ------------------------- fused flash attention -----------------------------
#define KPAD 264
#define VPAD 136
#define FSM_BYTES ((128 * KPAD * 2 + 128 * VPAD * 2) * 2)   // 204800
#define NCHUNK (TT / 128)

__global__ __launch_bounds__(256, 1) void flash_attn(
    const __nv_bfloat16* __restrict__ Qe,
    const __nv_bfloat16* __restrict__ Ke,
    const __nv_bfloat16* __restrict__ Ve,
    __nv_bfloat16* __restrict__ Oex)
{
    extern __shared__ char fsm[];
    const uint32_t uQ  = smem_u32(fsm);
    const uint32_t uK  = uQ + 128 * KPAD * 2;
    const uint32_t uVh = uK + 128 * KPAD * 2;
    const uint32_t uVl = uVh + 128 * VPAD * 2;

    const int t = threadIdx.x, wid = t >> 5, lid = t & 31;
    const int h = blockIdx.y, hk = h / GQA;
    const int q0 = blockIdx.x * 128;

    const __nv_bfloat16* Qg = Qe + ((long)h * TT + q0) * 256;
    const __nv_bfloat16* Kg = Ke + (long)hk * TT * 256;
    const __nv_bfloat16* Vg = Ve + (long)hk * HDIM * (2 * TT);

    auto loadK = [&](int kc) {
        const __nv_bfloat16* src = Kg + (long)kc * 128 * 256;
#pragma unroll
        for (int i = 0; i < 16; i++) {
            int idx = t + i * 256, row = idx >> 5, ce = (idx & 31) * 8;
            cp16(uK + (row * KPAD + ce) * 2, src + (long)row * 256 + ce);
        }
    };
    auto loadV = [&](int kc) {
#pragma unroll
        for (int i = 0; i < 8; i++) {
            int idx = t + i * 256, row = idx >> 4, ce = (idx & 15) * 8;
            const __nv_bfloat16* s = Vg + (long)row * (2 * TT) + kc * 128 + ce;
            cp16(uVh + (row * VPAD + ce) * 2, s);
            cp16(uVl + (row * VPAD + ce) * 2, s + TT);
        }
    };

#pragma unroll
    for (int i = 0; i < 16; i++) {
        int idx = t + i * 256, row = idx >> 5, ce = (idx & 31) * 8;
        cp16(uQ + (row * KPAD + ce) * 2, Qg + (long)row * 256 + ce);
    }
    loadK(0);
    loadV(0);
    asm volatile("cp.async.commit_group;" ::: "memory");
    asm volatile("cp.async.wait_group 0;" ::: "memory");
    __syncthreads();

    const int a_row = (lid & 7) + ((lid >> 3) & 1) * 8;
    const int a_c8  = (lid >> 4) * 8;
    const int b4r   = (lid & 7) + ((lid >> 4) & 1) * 8;
    const int b4c   = ((lid >> 3) & 1) * 8;
    const uint32_t aQbase = uQ + ((wid * 16 + a_row) * KPAD + a_c8) * 2;

    float oacc[16][4];
#pragma unroll
    for (int nj = 0; nj < 16; nj++)
#pragma unroll
        for (int r = 0; r < 4; r++) oacc[nj][r] = 0.0f;
    float m0 = -1e30f, m1 = -1e30f, l0 = 0.0f, l1 = 0.0f;

    for (int kc = 0; kc < NCHUNK; kc++) {
        if (kc > 0) {
            asm volatile("cp.async.wait_group 1;" ::: "memory");
            __syncthreads();
        }

        float sacc[16][4];
#pragma unroll
        for (int nj = 0; nj < 16; nj++)
#pragma unroll
            for (int r = 0; r < 4; r++) sacc[nj][r] = 0.0f;

#pragma unroll
        for (int ks = 0; ks < 8; ks++) {
            uint32_t aqh[4], aql[4];
            ldx4(aqh, aQbase + (ks * 16) * 2);
            ldx4(aql, aQbase + (128 + ks * 16) * 2);
#pragma unroll
            for (int njp = 0; njp < 8; njp++) {
                uint32_t bh[4], bl[4];
                ldx4(bh, uK + ((njp * 16 + b4r) * KPAD + ks * 16 + b4c) * 2);
                ldx4(bl, uK + ((njp * 16 + b4r) * KPAD + 128 + ks * 16 + b4c) * 2);
                hmma(sacc[2 * njp],     aqh, bh);
                hmma(sacc[2 * njp],     aql, bh);
                hmma(sacc[2 * njp],     aqh, bl);
                hmma(sacc[2 * njp + 1], aqh, bh + 2);
                hmma(sacc[2 * njp + 1], aql, bh + 2);
                hmma(sacc[2 * njp + 1], aqh, bl + 2);
            }
        }
        __syncthreads();
        if (kc + 1 < NCHUNK) {
            loadK(kc + 1);
            asm volatile("cp.async.commit_group;" ::: "memory");
        }

        float mx0 = -1e30f, mx1 = -1e30f;
#pragma unroll
        for (int nj = 0; nj < 16; nj++) {
            mx0 = fmaxf(mx0, fmaxf(sacc[nj][0], sacc[nj][1]));
            mx1 = fmaxf(mx1, fmaxf(sacc[nj][2], sacc[nj][3]));
        }
        mx0 = fmaxf(mx0, __shfl_xor_sync(0xffffffffu, mx0, 1));
        mx0 = fmaxf(mx0, __shfl_xor_sync(0xffffffffu, mx0, 2));
        mx1 = fmaxf(mx1, __shfl_xor_sync(0xffffffffu, mx1, 1));
        mx1 = fmaxf(mx1, __shfl_xor_sync(0xffffffffu, mx1, 2));
        float nm0 = fmaxf(m0, mx0), nm1 = fmaxf(m1, mx1);
        float sc0 = ex2(m0 - nm0), sc1 = ex2(m1 - nm1);
        m0 = nm0; m1 = nm1;
        l0 *= sc0; l1 *= sc1;
#pragma unroll
        for (int nj = 0; nj < 16; nj++) {
            oacc[nj][0] *= sc0; oacc[nj][1] *= sc0;
            oacc[nj][2] *= sc1; oacc[nj][3] *= sc1;
        }

        if (kc + 1 < NCHUNK) {
            asm volatile("cp.async.wait_group 1;" ::: "memory");
        } else {
            asm volatile("cp.async.wait_group 0;" ::: "memory");
        }
        __syncthreads();

#pragma unroll
        for (int ks = 0; ks < 8; ks++) {
            float e00 = ex2(sacc[2 * ks][0]     - m0);
            float e01 = ex2(sacc[2 * ks][1]     - m0);
            float e02 = ex2(sacc[2 * ks][2]     - m1);
            float e03 = ex2(sacc[2 * ks][3]     - m1);
            float e10 = ex2(sacc[2 * ks + 1][0] - m0);
            float e11 = ex2(sacc[2 * ks + 1][1] - m0);
            float e12 = ex2(sacc[2 * ks + 1][2] - m1);
            float e13 = ex2(sacc[2 * ks + 1][3] - m1);
            l0 += e00 + e01 + e10 + e11;
            l1 += e02 + e03 + e12 + e13;
            uint32_t ph[4], pl[4];
            packsplit(e00, e01, ph[0], pl[0]);
            packsplit(e02, e03, ph[1], pl[1]);
            packsplit(e10, e11, ph[2], pl[2]);
            packsplit(e12, e13, ph[3], pl[3]);
#pragma unroll
            for (int njp = 0; njp < 8; njp++) {
                uint32_t bvh[4], bvl[4];
                ldx4(bvh, uVh + ((njp * 16 + b4r) * VPAD + ks * 16 + b4c) * 2);
                ldx4(bvl, uVl + ((njp * 16 + b4r) * VPAD + ks * 16 + b4c) * 2);
                hmma(oacc[2 * njp],     ph, bvh);
                hmma(oacc[2 * njp],     pl, bvh);
                hmma(oacc[2 * njp],     ph, bvl);
                hmma(oacc[2 * njp + 1], ph, bvh + 2);
                hmma(oacc[2 * njp + 1], pl, bvh + 2);
                hmma(oacc[2 * njp + 1], ph, bvl + 2);
            }
        }
        __syncthreads();
        if (kc + 1 < NCHUNK) {
            loadV(kc + 1);
            asm volatile("cp.async.commit_group;" ::: "memory");
        }
    }

    l0 += __shfl_xor_sync(0xffffffffu, l0, 1);
    l0 += __shfl_xor_sync(0xffffffffu, l0, 2);
    l1 += __shfl_xor_sync(0xffffffffu, l1, 1);
    l1 += __shfl_xor_sync(0xffffffffu, l1, 2);
    const float inv0 = 1.0f / l0, inv1 = 1.0f / l1;

    const int gr = lid >> 2;
    const int ec = (lid & 3) * 2;
    const long r0 = q0 + wid * 16 + gr;
    const long r1 = r0 + 8;
#pragma unroll
    for (int nj = 0; nj < 16; nj++) {
        int col = h * HDIM + nj * 8 + ec;
        uint32_t hi, lo;
        packsplit(oacc[nj][0] * inv0, oacc[nj][1] * inv0, hi, lo);
        *(uint32_t*)(Oex + r0 * (2 * HIDD) + col)        = hi;
        *(uint32_t*)(Oex + r0 * (2 * HIDD) + HIDD + col) = lo;
        packsplit(oacc[nj][2] * inv1, oacc[nj][3] * inv1, hi, lo);
        *(uint32_t*)(Oex + r1 * (2 * HIDD) + col)        = hi;
        *(uint32_t*)(Oex + r1 * (2 * HIDD) + HIDD + col) = lo;
    }
}

// ------------------------- conversion kernels -------------------------------
__global__ void zero_out(float4* __restrict__ p, long n4)
{
    long i = (long)blockIdx.x * 256 + threadIdx.x;
    if (i < n4) p[i] = make_float4(0.f, 0.f, 0.f, 0.f);
}

__global__ void split_rows(const float* __restrict__ in, __nv_bfloat16* __restrict__ out,
                           int K)
{
    const int r = blockIdx.y;
    const int k = (blockIdx.x * 256 + threadIdx.x) * 4;
    if (k >= K) return;
    float4 x = *(const float4*)(in + (long)r * K + k);
    __nv_bfloat16 h0,l0,h1,l1,h2,l2,h3,l3;
    split2(x.x,h0,l0); split2(x.y,h1,l1); split2(x.z,h2,l2); split2(x.w,h3,l3);
    __nv_bfloat16* oh = out + (long)r * 2 * K + k;
    oh[0]=h0; oh[1]=h1; oh[2]=h2; oh[3]=h3;
    __nv_bfloat16* ol = oh + K;
    ol[0]=l0; ol[1]=l1; ol[2]=l2; ol[3]=l3;
}

// generic 64x64 transpose-split (used for V)
__global__ void split_transpose(const float* __restrict__ in, int ldin, long inBatch,
                                __nv_bfloat16* __restrict__ out, int Kdim, long outBatch)
{
    __shared__ float smt[64][65];
    const float* ip = in + (long)blockIdx.z * inBatch;
    __nv_bfloat16* op = out + (long)blockIdx.z * outBatch;
    const int k0 = blockIdx.x * 64, n0 = blockIdx.y * 64;
    const int tx = threadIdx.x, ty = threadIdx.y;

#pragma unroll
    for (int rr = 0; rr < 8; rr++) {
        int i = ty + rr * 8;
        float2 v = *(const float2*)(ip + (long)(k0 + i) * ldin + n0 + tx * 2);
        smt[i][tx * 2]     = v.x;
        smt[i][tx * 2 + 1] = v.y;
    }
    __syncthreads();

#pragma unroll
    for (int rr = 0; rr < 8; rr++) {
        int j = ty + rr * 8;
        float x0 = smt[tx * 2][j];
        float x1 = smt[tx * 2 + 1][j];
        uint32_t hi, lo;
        packsplit(x0, x1, hi, lo);
        long base = (long)(n0 + j) * (2L * Kdim) + k0 + tx * 2;
        *(uint32_t*)(op + base)        = hi;
        *(uint32_t*)(op + base + Kdim) = lo;
    }
}

// weight transpose-split with y-offset so QKV-part and WO-part launch separately.
__global__ void split_transpose_w(const float* __restrict__ wq, const float* __restrict__ wk,
                                  const float* __restrict__ wv, const float* __restrict__ wo,
                                  __nv_bfloat16* __restrict__ wqkvex,
                                  __nv_bfloat16* __restrict__ woex, int ybase)
{
    __shared__ float smt[64][65];
    int yb = blockIdx.y + ybase;
    const float* src; int ldin; __nv_bfloat16* dst;
    if (yb < 56)       { src = wq; ldin = HIDD; dst = wqkvex; }
    else if (yb < 64)  { src = wk; ldin = 512;  dst = wqkvex + (size_t)HIDD * 2 * HIDD;        yb -= 56; }
    else if (yb < 72)  { src = wv; ldin = 512;  dst = wqkvex + (size_t)(HIDD + 512) * 2 * HIDD; yb -= 64; }
    else               { src = wo; ldin = HIDD; dst = woex;                                     yb -= 72; }

    const int k0 = blockIdx.x * 64, n0 = yb * 64;
    const int tx = threadIdx.x, ty = threadIdx.y;

#pragma unroll
    for (int rr = 0; rr < 8; rr++) {
        int i = ty + rr * 8;
        float2 v = *(const float2*)(src + (long)(k0 + i) * ldin + n0 + tx * 2);
        smt[i][tx * 2]     = v.x;
        smt[i][tx * 2 + 1] = v.y;
    }
    __syncthreads();

#pragma unroll
    for (int rr = 0; rr < 8; rr++) {
        int j = ty + rr * 8;
        float x0 = smt[tx * 2][j];
        float x1 = smt[tx * 2 + 1][j];
        uint32_t hi, lo;
        packsplit(x0, x1, hi, lo);
        long base = (long)(n0 + j) * (2L * HIDD) + k0 + tx * 2;
        *(uint32_t*)(dst + base)        = hi;
        *(uint32_t*)(dst + base + HIDD) = lo;
    }
}

__global__ void rope_tab(const int* __restrict__ pos, float* __restrict__ tab)
{
    int t = blockIdx.x, d = threadIdx.x;
    float p = (float)pos[t];
    float ang = p * exp2f(-(float)d * (LOG2_THETA / 64.0f));
    float s, c;
    sincosf(ang, &s, &c);
    tab[t * 128 + d]      = c;
    tab[t * 128 + 64 + d] = s;
}

// merged RoPE + scale + split for Q and K. grid (TT/4, 32): y<28 -> Q head, else K head.
__global__ void rope_split(const float* __restrict__ qkv,
                           const float* __restrict__ tab,
                           __nv_bfloat16* __restrict__ qex,
                           __nv_bfloat16* __restrict__ kex)
{
    int d   = threadIdx.x & 63;
    int sub = threadIdx.x >> 6;
    int t   = blockIdx.x * 4 + sub;
    int h   = blockIdx.y;
    const float* row;
    __nv_bfloat16* o;
    float scale;
    if (h < NHQ) {
        row = qkv + (long)t * NQKV + h * HDIM;
        o   = qex + ((long)h * TT + t) * (2 * HDIM);
        scale = SCALE_L2E;
    } else {
        int hk = h - NHQ;
        row = qkv + (long)t * NQKV + HIDD + hk * HDIM;
        o   = kex + ((long)hk * TT + t) * (2 * HDIM);
        scale = 1.0f;
    }
    float c = tab[t * 128 + d];
    float s = tab[t * 128 + 64 + d];
    float x1 = row[d], x2 = row[d + 64];
    float y1 = (x1 * c - x2 * s) * scale;
    float y2 = (x2 * c + x1 * s) * scale;
    __nv_bfloat16 h1, l1, h2, l2;
    split2(y1, h1, l1); split2(y2, h2, l2);
    o[d] = h1; o[d + 64] = h2;
    o[128 + d] = l1; o[128 + d + 64] = l2;
}

__global__ void concat_bias(const float* __restrict__ bq, const float* __restrict__ bk,
                            const float* __restrict__ bv, float* __restrict__ o)
{
    int i = blockIdx.x * 256 + threadIdx.x;
    if (i >= NQKV) return;
    if (i < HIDD)            o[i] = bq[i];
    else if (i < HIDD + 512) o[i] = bk[i - HIDD];
    else                     o[i] = bv[i - HIDD - 512];
}

// ------------------------- streams/events (created once at static init) -----
struct GraphStreams {
    cudaStream_t s1 = nullptr, s2 = nullptr;
    cudaEvent_t eRoot = nullptr, eW1 = nullptr, eAux = nullptr, eWo = nullptr;
    GraphStreams() {
        cudaStreamCreateWithFlags(&s1, cudaStreamNonBlocking);
        cudaStreamCreateWithFlags(&s2, cudaStreamNonBlocking);
        cudaEventCreateWithFlags(&eRoot, cudaEventDisableTiming);
        cudaEventCreateWithFlags(&eW1,   cudaEventDisableTiming);
        cudaEventCreateWithFlags(&eAux,  cudaEventDisableTiming);
        cudaEventCreateWithFlags(&eWo,   cudaEventDisableTiming);
    }
};
static GraphStreams g_gs;

// ------------------------- launch -------------------------------------------
extern "C" void kernel_launch(void* const* d_in, const int* in_sizes, int n_in,
                              void* d_out, int out_size)
{
    const int*   pos = (const int*)d_in[0];
    const float* hs  = (const float*)d_in[1];
    const float* wq  = (const float*)d_in[2];
    const float* bq  = (const float*)d_in[3];
    const float* wk  = (const float*)d_in[4];
    const float* bk  = (const float*)d_in[5];
    const float* wv  = (const float*)d_in[6];
    const float* bv  = (const float*)d_in[7];
    const float* wo  = (const float*)d_in[8];
    float* out = (float*)d_out;

    __nv_bfloat16 *hsex, *wqkvex, *woex, *qex, *kex, *vex, *attnex;
    float *qkv, *bqkv, *rtab;
    cudaGetSymbolAddress((void**)&hsex,   g_hsex);
    cudaGetSymbolAddress((void**)&wqkvex, g_wqkvex);
    cudaGetSymbolAddress((void**)&bqkv,   g_bqkv);
    cudaGetSymbolAddress((void**)&woex,   g_woex);
    cudaGetSymbolAddress((void**)&qkv,    g_qkv);
    cudaGetSymbolAddress((void**)&qex,    g_qex);
    cudaGetSymbolAddress((void**)&kex,    g_kex);
    cudaGetSymbolAddress((void**)&vex,    g_vex);
    cudaGetSymbolAddress((void**)&attnex, g_attnex);
    cudaGetSymbolAddress((void**)&rtab,   g_rtab);

    const int smem128 = STAGES * (128 + 128) * APAD * 2;
    cudaFuncSetAttribute(mma_gemm<false>, cudaFuncAttributeMaxDynamicSharedMemorySize, smem128);
    cudaFuncSetAttribute(mma_gemm<true>,  cudaFuncAttributeMaxDynamicSharedMemorySize, smem128);
    cudaFuncSetAttribute(flash_attn,      cudaFuncAttributeMaxDynamicSharedMemorySize, FSM_BYTES);

    // fork side streams from the main (capture) stream
    cudaEventRecord(g_gs.eRoot, 0);
    cudaStreamWaitEvent(g_gs.s1, g_gs.eRoot, 0);
    cudaStreamWaitEvent(g_gs.s2, g_gs.eRoot, 0);

    // s1: QKV weights transpose (needed by QKV GEMM), then WO transpose (needed only by O-proj)
    split_transpose_w<<<dim3(HIDD/64, 72), dim3(32,8), 0, g_gs.s1>>>(
        wq, wk, wv, wo, wqkvex, woex, 0);
    cudaEventRecord(g_gs.eW1, g_gs.s1);
    split_transpose_w<<<dim3(HIDD/64, 56), dim3(32,8), 0, g_gs.s1>>>(
        wq, wk, wv, wo, wqkvex, woex, 72);
    cudaEventRecord(g_gs.eWo, g_gs.s1);

    // s2: bias concat + rope table + output zero-init
    concat_bias<<<(NQKV + 255) / 256, 256, 0, g_gs.s2>>>(bq, bk, bv, bqkv);
    rope_tab<<<TT, 64, 0, g_gs.s2>>>(pos, rtab);
    {
        long n4 = (long)TT * HIDD / 4;
        zero_out<<<(unsigned)((n4 + 255) / 256), 256, 0, g_gs.s2>>>((float4*)out, n4);
    }
    cudaEventRecord(g_gs.eAux, g_gs.s2);

    // main stream: hidden-state split (concurrent with s1/s2)
    split_rows<<<dim3((HIDD/4 + 255) / 256, TT), 256>>>(hs, hsex, HIDD);

    // join QKV weights + aux before QKV GEMM / rope_split
    cudaStreamWaitEvent(0, g_gs.eW1, 0);
    cudaStreamWaitEvent(0, g_gs.eAux, 0);

    // ---- fused QKV projection (WO transpose keeps running on s1) ----
    mma_gemm<false><<<dim3(NQKV/128, TT/128, 1), 256, smem128>>>(
        hsex, wqkvex, bqkv, qkv, NQKV, HIDD, 1.0f);

    // ---- RoPE (Q scaled) + split; V transpose + split ----
    rope_split<<<dim3(TT/4, NHQ + NKVH), 256>>>(qkv, rtab, qex, kex);
    split_transpose<<<dim3(TT/64, HDIM/64, NKVH), dim3(32,8)>>>(
        qkv + HIDD + 512, NQKV, (long)HDIM, vex, TT, (long)HDIM * 2 * TT);

    // ---- fused attention ----
    flash_attn<<<dim3(TT/128, NHQ), 256, FSM_BYTES>>>(qex, kex, vex, attnex);

    // join WO transpose before O-projection
    cudaStreamWaitEvent(0, g_gs.eWo, 0);

    // ---- out = attn @ wo  (split-K=2, red.add into zeroed out) ----
    mma_gemm<true><<<dim3(HIDD/128, TT/128, 2), 256, smem128>>>(
        attnex, woex, nullptr, out, HIDD, HIDD, 1.0f);
}